// round 6
// baseline (speedup 1.0000x reference)
#include <cuda_runtime.h>
#include <math.h>
#include <stdint.h>

// Problem constants (B=2, S=2048, H=1024, E=8, I=4096, K=2)
#define Tn 4096
#define Hd 1024
#define Id 4096
#define Ed 8

// ---------------- device scratch ----------------
__device__ int   g_count[Ed];
__device__ int   g_count2[Ed];
__device__ int   g_offset[Ed];
__device__ int   g_top_e[Tn * 2];
__device__ float g_top_w[Tn * 2];
__device__ int   g_row_tok[Tn * 2];
__device__ int   g_tok_row[Tn * 2];
__device__ float g_hidden[(size_t)Tn * 2 * Id];  // 134 MB
__device__ float g_down[(size_t)Tn * 2 * Hd];    // 33.5 MB

// ---------------- helpers ----------------
__device__ __forceinline__ uint32_t smem_u32(const void* p) {
    uint32_t a;
    asm("{ .reg .u64 t; cvta.to.shared.u64 t, %1; cvt.u32.u64 %0, t; }" : "=r"(a) : "l"(p));
    return a;
}
__device__ __forceinline__ uint32_t f2tf32(float f) {
    uint32_t r; asm("cvt.rna.tf32.f32 %0, %1;" : "=r"(r) : "f"(f)); return r;
}
#define MMA_TF32(c, a, b0, b1) \
    asm volatile("mma.sync.aligned.m16n8k8.row.col.f32.tf32.tf32.f32 " \
                 "{%0,%1,%2,%3}, {%4,%5,%6,%7}, {%8,%9}, {%0,%1,%2,%3};" \
                 : "+f"((c)[0]), "+f"((c)[1]), "+f"((c)[2]), "+f"((c)[3]) \
                 : "r"((a)[0]), "r"((a)[1]), "r"((a)[2]), "r"((a)[3]), \
                   "r"(b0), "r"(b1))
#define CP16(dst_u32, src_ptr) \
    asm volatile("cp.async.cg.shared.global [%0], [%1], 16;" :: "r"(dst_u32), "l"(src_ptr))
__device__ __forceinline__ void cp_commit() { asm volatile("cp.async.commit_group;" ::: "memory"); }
__device__ __forceinline__ void cp_wait1()  { asm volatile("cp.async.wait_group 1;" ::: "memory"); }
__device__ __forceinline__ void cp_wait0()  { asm volatile("cp.async.wait_group 0;" ::: "memory"); }

// ---------------- init / router / scan / assign ----------------
__global__ void k_init() {
    int i = threadIdx.x;
    if (i < Ed) { g_count[i] = 0; g_count2[i] = 0; }
}

__global__ void __launch_bounds__(256) k_router(const float* __restrict__ x,
                                                const float* __restrict__ gw) {
    __shared__ float sgw[Ed * Hd];
    int tid = threadIdx.x;
    for (int i = tid; i < Ed * Hd; i += 256) sgw[i] = gw[i];
    __syncthreads();
    int warp = tid >> 5, lane = tid & 31;
    int t = blockIdx.x * 8 + warp;
    float acc[Ed];
#pragma unroll
    for (int e = 0; e < Ed; e++) acc[e] = 0.f;
    const float* xr = x + (size_t)t * Hd;
    for (int h = lane; h < Hd; h += 32) {
        float xv = xr[h];
#pragma unroll
        for (int e = 0; e < Ed; e++) acc[e] += xv * sgw[e * Hd + h];
    }
#pragma unroll
    for (int e = 0; e < Ed; e++) {
#pragma unroll
        for (int o = 16; o > 0; o >>= 1) acc[e] += __shfl_xor_sync(0xffffffffu, acc[e], o);
    }
    if (lane == 0) {
        float v0 = -1e30f; int e0 = 0;
#pragma unroll
        for (int e = 0; e < Ed; e++) if (acc[e] > v0) { v0 = acc[e]; e0 = e; }
        float v1 = -1e30f; int e1 = 0;
#pragma unroll
        for (int e = 0; e < Ed; e++) if (e != e0 && acc[e] > v1) { v1 = acc[e]; e1 = e; }
        float r  = expf(v1 - v0);
        float w0 = 1.f / (1.f + r);
        float w1 = r / (1.f + r);
        g_top_e[t * 2] = e0;  g_top_e[t * 2 + 1] = e1;
        g_top_w[t * 2] = w0;  g_top_w[t * 2 + 1] = w1;
        atomicAdd(&g_count[e0], 1);
        atomicAdd(&g_count[e1], 1);
    }
}

__global__ void k_scan() {
    int off = 0;
    for (int e = 0; e < Ed; e++) { g_offset[e] = off; off += g_count[e]; }
}

__global__ void __launch_bounds__(256) k_assign() {
    int t = blockIdx.x * 256 + threadIdx.x;
    if (t >= Tn) return;
#pragma unroll
    for (int k = 0; k < 2; k++) {
        int e   = g_top_e[t * 2 + k];
        int pos = atomicAdd(&g_count2[e], 1);
        int row = g_offset[e] + pos;
        g_row_tok[row]       = t;
        g_tok_row[t * 2 + k] = row;
    }
}

// ================= GEMM1: hidden = silu(x@wg^T) * (x@wu^T) =================
// CTA 128m x 128n, K-chunk 32. 8 warps = 2m x 4n; warp 64m x 32n DUAL (gate+up).
// SMEM holds raw fp32 (cp.async); tf32 cvt at fragment load.
// Buffer: A[128][36] | Bg[128][36] | Bu[128][36]
#define G1_BUF (3 * 128 * 36)                 // floats
#define G1_SMEM ((128 + 2 * G1_BUF) * 4)      // 111104 B
__global__ void __launch_bounds__(256) k_gemm1(const float* __restrict__ x,
                                               const float* __restrict__ wg,
                                               const float* __restrict__ wu) {
    int e   = blockIdx.z;
    int cnt = g_count[e];
    int m0  = blockIdx.x * 128;
    if (m0 >= cnt) return;
    int off = g_offset[e];
    int n0  = blockIdx.y * 128;

    extern __shared__ float smf[];
    int* toks = (int*)smf;
    float* bufs = smf + 128;

    int tid = threadIdx.x;
    int lane = tid & 31, wid = tid >> 5;
    int warp_m = wid >> 2, warp_n = wid & 3;   // 2 x 4
    int g = lane >> 2, tig = lane & 3;

    for (int i = tid; i < 128; i += 256) {
        int m = m0 + i; if (m >= cnt) m = cnt - 1;
        toks[i] = g_row_tok[off + m];
    }
    __syncthreads();

    // load slots: 128 rows x 8 quads = 1024 per matrix; 4 slots/thread/matrix
    const float* wgE = wg + (size_t)e * Id * Hd;
    const float* wuE = wu + (size_t)e * Id * Hd;
    const float* agm[4]; const float* ggm[4]; const float* ugm[4];
    uint32_t soff[4];
#pragma unroll
    for (int p = 0; p < 4; p++) {
        int idx = tid + 256 * p;
        int r = idx >> 3, c4 = (idx & 7) * 4;
        agm[p] = x + (size_t)toks[r] * Hd + c4;
        ggm[p] = wgE + (size_t)(n0 + r) * Hd + c4;
        ugm[p] = wuE + (size_t)(n0 + r) * Hd + c4;
        soff[p] = (r * 36 + c4) * 4;           // byte offset within region
    }
    uint32_t smb = smem_u32(bufs);

    float cg[4][4][4] = {}, cu[4][4][4] = {};

    // prologue: chunk 0 -> buf 0
#pragma unroll
    for (int p = 0; p < 4; p++) {
        CP16(smb + soff[p],                  agm[p]);
        CP16(smb + 128 * 36 * 4 + soff[p],   ggm[p]);
        CP16(smb + 256 * 36 * 4 + soff[p],   ugm[p]);
    }
    cp_commit();

    const int NCH = Hd / 32;  // 32
    for (int ch = 0; ch < NCH; ch++) {
        int buf = ch & 1;
        if (ch + 1 < NCH) {
            int k0 = (ch + 1) * 32;
            uint32_t base = smb + (buf ^ 1) * (G1_BUF * 4);
#pragma unroll
            for (int p = 0; p < 4; p++) {
                CP16(base + soff[p],                agm[p] + k0);
                CP16(base + 128 * 36 * 4 + soff[p], ggm[p] + k0);
                CP16(base + 256 * 36 * 4 + soff[p], ugm[p] + k0);
            }
            cp_commit();
            cp_wait1();
        } else {
            cp_wait0();
        }
        __syncthreads();

        const float* A  = bufs + buf * G1_BUF;
        const float* Bg = A + 128 * 36;
        const float* Bu = Bg + 128 * 36;
#pragma unroll
        for (int ks = 0; ks < 4; ks++) {
            int kc = ks * 8;
            uint32_t a[4][4];
#pragma unroll
            for (int i = 0; i < 4; i++) {
                int r = warp_m * 64 + i * 16 + g;
                a[i][0] = f2tf32(A[r * 36 + kc + tig]);
                a[i][1] = f2tf32(A[(r + 8) * 36 + kc + tig]);
                a[i][2] = f2tf32(A[r * 36 + kc + tig + 4]);
                a[i][3] = f2tf32(A[(r + 8) * 36 + kc + tig + 4]);
            }
#pragma unroll
            for (int j = 0; j < 4; j++) {
                int n = warp_n * 32 + j * 8 + g;
                uint32_t bg0 = f2tf32(Bg[n * 36 + kc + tig]);
                uint32_t bg1 = f2tf32(Bg[n * 36 + kc + tig + 4]);
                uint32_t bu0 = f2tf32(Bu[n * 36 + kc + tig]);
                uint32_t bu1 = f2tf32(Bu[n * 36 + kc + tig + 4]);
#pragma unroll
                for (int i = 0; i < 4; i++) {
                    MMA_TF32(cg[i][j], a[i], bg0, bg1);
                    MMA_TF32(cu[i][j], a[i], bu0, bu1);
                }
            }
        }
        __syncthreads();
    }

    // epilogue: silu(gate)*up -> g_hidden
#pragma unroll
    for (int i = 0; i < 4; i++) {
        int rb = m0 + warp_m * 64 + i * 16 + g;
#pragma unroll
        for (int j = 0; j < 4; j++) {
            int n = n0 + warp_n * 32 + j * 8 + 2 * tig;
            if (rb < cnt) {
                size_t base = (size_t)(off + rb) * Id + n;
                float g0 = cg[i][j][0], g1 = cg[i][j][1];
                g_hidden[base]     = g0 / (1.f + expf(-g0)) * cu[i][j][0];
                g_hidden[base + 1] = g1 / (1.f + expf(-g1)) * cu[i][j][1];
            }
            if (rb + 8 < cnt) {
                size_t base = (size_t)(off + rb + 8) * Id + n;
                float g2 = cg[i][j][2], g3 = cg[i][j][3];
                g_hidden[base]     = g2 / (1.f + expf(-g2)) * cu[i][j][2];
                g_hidden[base + 1] = g3 / (1.f + expf(-g3)) * cu[i][j][3];
            }
        }
    }
}

// ================= GEMM2: down = hidden @ wd^T =================
// CTA 256m x 128n, K-chunk 32. 8 warps = 4m x 2n; warp 64m x 64n.
// Buffer: A[256][36] | B[128][36]
#define G2_BUF ((256 + 128) * 36)             // floats
#define G2_SMEM (2 * G2_BUF * 4)              // 110592 B
__global__ void __launch_bounds__(256) k_gemm2(const float* __restrict__ wd) {
    int e   = blockIdx.z;
    int cnt = g_count[e];
    int m0  = blockIdx.x * 256;
    if (m0 >= cnt) return;
    int off = g_offset[e];
    int n0  = blockIdx.y * 128;

    extern __shared__ float smf[];
    float* bufs = smf;

    int tid = threadIdx.x;
    int lane = tid & 31, wid = tid >> 5;
    int warp_m = wid & 3, warp_n = wid >> 2;   // 4 x 2
    int g = lane >> 2, tig = lane & 3;

    const float* wdE = wd + (size_t)e * Hd * Id;
    // A: 256 rows x 8 quads = 2048 slots -> 8/thread; B: 128 rows -> 4/thread
    const float* agm[8]; uint32_t aoff[8];
    const float* bgm[4]; uint32_t boff[4];
#pragma unroll
    for (int p = 0; p < 8; p++) {
        int idx = tid + 256 * p;
        int r = idx >> 3, c4 = (idx & 7) * 4;
        int am = m0 + r; if (am >= cnt) am = cnt - 1;
        agm[p] = g_hidden + (size_t)(off + am) * Id + c4;
        aoff[p] = (r * 36 + c4) * 4;
    }
#pragma unroll
    for (int p = 0; p < 4; p++) {
        int idx = tid + 256 * p;
        int r = idx >> 3, c4 = (idx & 7) * 4;
        bgm[p] = wdE + (size_t)(n0 + r) * Id + c4;
        boff[p] = (256 * 36 + r * 36 + c4) * 4;
    }
    uint32_t smb = smem_u32(bufs);

    float c[4][8][4] = {};

#pragma unroll
    for (int p = 0; p < 8; p++) CP16(smb + aoff[p], agm[p]);
#pragma unroll
    for (int p = 0; p < 4; p++) CP16(smb + boff[p], bgm[p]);
    cp_commit();

    const int NCH = Id / 32;  // 128
    for (int ch = 0; ch < NCH; ch++) {
        int buf = ch & 1;
        if (ch + 1 < NCH) {
            int k0 = (ch + 1) * 32;
            uint32_t base = smb + (buf ^ 1) * (G2_BUF * 4);
#pragma unroll
            for (int p = 0; p < 8; p++) CP16(base + aoff[p], agm[p] + k0);
#pragma unroll
            for (int p = 0; p < 4; p++) CP16(base + boff[p], bgm[p] + k0);
            cp_commit();
            cp_wait1();
        } else {
            cp_wait0();
        }
        __syncthreads();

        const float* A = bufs + buf * G2_BUF;
        const float* B = A + 256 * 36;
#pragma unroll
        for (int ks = 0; ks < 4; ks++) {
            int kc = ks * 8;
            uint32_t a[4][4];
#pragma unroll
            for (int i = 0; i < 4; i++) {
                int r = warp_m * 64 + i * 16 + g;
                a[i][0] = f2tf32(A[r * 36 + kc + tig]);
                a[i][1] = f2tf32(A[(r + 8) * 36 + kc + tig]);
                a[i][2] = f2tf32(A[r * 36 + kc + tig + 4]);
                a[i][3] = f2tf32(A[(r + 8) * 36 + kc + tig + 4]);
            }
#pragma unroll
            for (int j = 0; j < 8; j++) {
                int n = warp_n * 64 + j * 8 + g;
                uint32_t b0 = f2tf32(B[n * 36 + kc + tig]);
                uint32_t b1 = f2tf32(B[n * 36 + kc + tig + 4]);
#pragma unroll
                for (int i = 0; i < 4; i++) MMA_TF32(c[i][j], a[i], b0, b1);
            }
        }
        __syncthreads();
    }

#pragma unroll
    for (int i = 0; i < 4; i++) {
        int rb = m0 + warp_m * 64 + i * 16 + g;
#pragma unroll
        for (int j = 0; j < 8; j++) {
            int n = n0 + warp_n * 64 + j * 8 + 2 * tig;
            if (rb < cnt) {
                size_t base = (size_t)(off + rb) * Hd + n;
                g_down[base]     = c[i][j][0];
                g_down[base + 1] = c[i][j][1];
            }
            if (rb + 8 < cnt) {
                size_t base = (size_t)(off + rb + 8) * Hd + n;
                g_down[base]     = c[i][j][2];
                g_down[base + 1] = c[i][j][3];
            }
        }
    }
}

// ---------------- combine ----------------
__global__ void __launch_bounds__(256) k_combine(float* __restrict__ out) {
    int idx = blockIdx.x * 256 + threadIdx.x;
    int t   = idx >> 8;
    int c4  = (idx & 255) << 2;
    int r0  = g_tok_row[t * 2];
    int r1  = g_tok_row[t * 2 + 1];
    float w0 = g_top_w[t * 2];
    float w1 = g_top_w[t * 2 + 1];
    float4 d0 = *(const float4*)(g_down + (size_t)r0 * Hd + c4);
    float4 d1 = *(const float4*)(g_down + (size_t)r1 * Hd + c4);
    float4 o;
    o.x = w0 * d0.x + w1 * d1.x;
    o.y = w0 * d0.y + w1 * d1.y;
    o.z = w0 * d0.z + w1 * d1.z;
    o.w = w0 * d0.w + w1 * d1.w;
    *(float4*)(out + (size_t)t * Hd + c4) = o;
}

// ---------------- launch ----------------
extern "C" void kernel_launch(void* const* d_in, const int* in_sizes, int n_in,
                              void* d_out, int out_size) {
    const float* x  = (const float*)d_in[0];
    const float* gw = (const float*)d_in[1];
    const float* wg = (const float*)d_in[2];
    const float* wu = (const float*)d_in[3];
    const float* wd = (const float*)d_in[4];
    float* out = (float*)d_out;

    cudaFuncSetAttribute(k_gemm1, cudaFuncAttributeMaxDynamicSharedMemorySize, G1_SMEM);
    cudaFuncSetAttribute(k_gemm2, cudaFuncAttributeMaxDynamicSharedMemorySize, G2_SMEM);

    k_init<<<1, 32>>>();
    k_router<<<Tn / 8, 256>>>(x, gw);
    k_scan<<<1, 1>>>();
    k_assign<<<Tn / 256, 256>>>();

    dim3 g1(32, 32, Ed);   // m-tiles(128) x n-tiles(128 over I) x experts (early-exit)
    k_gemm1<<<g1, 256, G1_SMEM>>>(x, wg, wu);

    dim3 g2(16, 8, Ed);    // m-tiles(256) x n-tiles(128 over H) x experts (early-exit)
    k_gemm2<<<g2, 256, G2_SMEM>>>(wd);

    k_combine<<<Tn * Hd / 1024, 256>>>(out);
}

// round 9
// speedup vs baseline: 1.5644x; 1.5644x over previous
#include <cuda_runtime.h>
#include <cuda_fp16.h>
#include <math.h>
#include <stdint.h>

// Problem constants (B=2, S=2048, H=1024, E=8, I=4096, K=2)
#define Tn 4096
#define Hd 1024
#define Id 4096
#define Ed 8

// ---------------- device scratch ----------------
__device__ int    g_count[Ed];
__device__ int    g_count2[Ed];
__device__ int    g_offset[Ed];
__device__ int    g_top_e[Tn * 2];
__device__ float  g_top_w[Tn * 2];
__device__ int    g_row_tok[Tn * 2];
__device__ int    g_tok_row[Tn * 2];
// fp16 mirrors — MUST be 16B+ aligned: cp.async 16B and __half2 accesses trap on misalignment
__device__ __align__(256) __half g_xh[(size_t)Tn * Hd];            // 8 MB
__device__ __align__(256) __half g_wgh[(size_t)Ed * Id * Hd];      // 64 MB
__device__ __align__(256) __half g_wuh[(size_t)Ed * Id * Hd];      // 64 MB
__device__ __align__(256) __half g_wdh[(size_t)Ed * Hd * Id];      // 64 MB
__device__ __align__(256) __half g_hidden_h[(size_t)Tn * 2 * Id];  // 67 MB
__device__ __align__(256) float  g_down[(size_t)Tn * 2 * Hd];      // 33.5 MB

// ---------------- helpers ----------------
__device__ __forceinline__ uint32_t smem_u32(const void* p) {
    uint32_t a;
    asm("{ .reg .u64 t; cvta.to.shared.u64 t, %1; cvt.u32.u64 %0, t; }" : "=r"(a) : "l"(p));
    return a;
}
#define MMA_F16(c, a, b0, b1) \
    asm volatile("mma.sync.aligned.m16n8k16.row.col.f32.f16.f16.f32 " \
                 "{%0,%1,%2,%3}, {%4,%5,%6,%7}, {%8,%9}, {%0,%1,%2,%3};" \
                 : "+f"((c)[0]), "+f"((c)[1]), "+f"((c)[2]), "+f"((c)[3]) \
                 : "r"((a)[0]), "r"((a)[1]), "r"((a)[2]), "r"((a)[3]), \
                   "r"(b0), "r"(b1))
#define CP16(dst_u32, src_ptr) \
    asm volatile("cp.async.cg.shared.global [%0], [%1], 16;" :: "r"(dst_u32), "l"(src_ptr))
__device__ __forceinline__ void cp_commit() { asm volatile("cp.async.commit_group;" ::: "memory"); }
__device__ __forceinline__ void cp_wait1()  { asm volatile("cp.async.wait_group 1;" ::: "memory"); }
__device__ __forceinline__ void cp_wait0()  { asm volatile("cp.async.wait_group 0;" ::: "memory"); }

// ---------------- fp32 -> fp16 converts (write __device__ symbols directly) ----------------
__device__ __forceinline__ void cvt8(const float* __restrict__ src,
                                     __half* __restrict__ dst, size_t i8) {
    size_t base = i8 * 8;
    float4 a = *(const float4*)(src + base);
    float4 b = *(const float4*)(src + base + 4);
    __half2* d = (__half2*)(dst + base);
    d[0] = __floats2half2_rn(a.x, a.y);
    d[1] = __floats2half2_rn(a.z, a.w);
    d[2] = __floats2half2_rn(b.x, b.y);
    d[3] = __floats2half2_rn(b.z, b.w);
}
__global__ void __launch_bounds__(256) k_cvt_x(const float* __restrict__ src) {
    int i = blockIdx.x * 256 + threadIdx.x;
    if (i < Tn * Hd / 8) cvt8(src, g_xh, i);
}
__global__ void __launch_bounds__(256) k_cvt_wg(const float* __restrict__ src) {
    int i = blockIdx.x * 256 + threadIdx.x;
    if (i < Ed * Id * Hd / 8) cvt8(src, g_wgh, i);
}
__global__ void __launch_bounds__(256) k_cvt_wu(const float* __restrict__ src) {
    int i = blockIdx.x * 256 + threadIdx.x;
    if (i < Ed * Id * Hd / 8) cvt8(src, g_wuh, i);
}
__global__ void __launch_bounds__(256) k_cvt_wd(const float* __restrict__ src) {
    int i = blockIdx.x * 256 + threadIdx.x;
    if (i < Ed * Hd * Id / 8) cvt8(src, g_wdh, i);
}

// ---------------- init / router / scan / assign ----------------
__global__ void k_init() {
    int i = threadIdx.x;
    if (i < Ed) { g_count[i] = 0; g_count2[i] = 0; }
}

__global__ void __launch_bounds__(256) k_router(const float* __restrict__ x,
                                                const float* __restrict__ gw) {
    __shared__ float sgw[Ed * Hd];
    int tid = threadIdx.x;
    for (int i = tid; i < Ed * Hd; i += 256) sgw[i] = gw[i];
    __syncthreads();
    int warp = tid >> 5, lane = tid & 31;
    int t = blockIdx.x * 8 + warp;
    float acc[Ed];
#pragma unroll
    for (int e = 0; e < Ed; e++) acc[e] = 0.f;
    const float* xr = x + (size_t)t * Hd;
    for (int h = lane; h < Hd; h += 32) {
        float xv = xr[h];
#pragma unroll
        for (int e = 0; e < Ed; e++) acc[e] += xv * sgw[e * Hd + h];
    }
#pragma unroll
    for (int e = 0; e < Ed; e++) {
#pragma unroll
        for (int o = 16; o > 0; o >>= 1) acc[e] += __shfl_xor_sync(0xffffffffu, acc[e], o);
    }
    if (lane == 0) {
        float v0 = -1e30f; int e0 = 0;
#pragma unroll
        for (int e = 0; e < Ed; e++) if (acc[e] > v0) { v0 = acc[e]; e0 = e; }
        float v1 = -1e30f; int e1 = 0;
#pragma unroll
        for (int e = 0; e < Ed; e++) if (e != e0 && acc[e] > v1) { v1 = acc[e]; e1 = e; }
        float r  = expf(v1 - v0);
        float w0 = 1.f / (1.f + r);
        float w1 = r / (1.f + r);
        g_top_e[t * 2] = e0;  g_top_e[t * 2 + 1] = e1;
        g_top_w[t * 2] = w0;  g_top_w[t * 2 + 1] = w1;
        atomicAdd(&g_count[e0], 1);
        atomicAdd(&g_count[e1], 1);
    }
}

__global__ void k_scan() {
    int off = 0;
    for (int e = 0; e < Ed; e++) { g_offset[e] = off; off += g_count[e]; }
}

__global__ void __launch_bounds__(256) k_assign() {
    int t = blockIdx.x * 256 + threadIdx.x;
    if (t >= Tn) return;
#pragma unroll
    for (int k = 0; k < 2; k++) {
        int e   = g_top_e[t * 2 + k];
        int pos = atomicAdd(&g_count2[e], 1);
        int row = g_offset[e] + pos;
        g_row_tok[row]       = t;
        g_tok_row[t * 2 + k] = row;
    }
}

// ================= GEMM1 (fp16 MMA): hidden = silu(x@wg^T) * (x@wu^T) =================
// CTA 128m x 128n, K-chunk 32 halves. 8 warps = 2m x 4n; warp 64m x 32n DUAL.
// SMEM rows padded to 40 halves (80 B). Buf: A[128][40] | Bg[128][40] | Bu[128][40]
#define G1_ROWB 80
#define G1_MATB (128 * G1_ROWB)               // 10240 B per matrix
#define G1_BUFB (3 * G1_MATB)                 // 30720 B per buffer
#define G1_SMEM (512 + 2 * G1_BUFB)           // 61952 B
__global__ void __launch_bounds__(256) k_gemm1() {
    int e   = blockIdx.z;
    int cnt = g_count[e];
    int m0  = blockIdx.x * 128;
    if (m0 >= cnt) return;
    int off = g_offset[e];
    int n0  = blockIdx.y * 128;

    extern __shared__ char smc[];
    int* toks = (int*)smc;
    char* bufs = smc + 512;

    int tid = threadIdx.x;
    int lane = tid & 31, wid = tid >> 5;
    int warp_m = wid >> 2, warp_n = wid & 3;   // 2 x 4
    int g = lane >> 2, tig = lane & 3;

    for (int i = tid; i < 128; i += 256) {
        int m = m0 + i; if (m >= cnt) m = cnt - 1;
        toks[i] = g_row_tok[off + m];
    }
    __syncthreads();

    // cp.async slots: 128 rows x 4 quads(16B) = 512 per matrix; 2 per thread
    const __half* wgE = g_wgh + (size_t)e * Id * Hd;
    const __half* wuE = g_wuh + (size_t)e * Id * Hd;
    const __half* agm[2]; const __half* ggm[2]; const __half* ugm[2];
    uint32_t soff[2];
#pragma unroll
    for (int p = 0; p < 2; p++) {
        int idx = tid + 256 * p;
        int r = idx >> 2, c = idx & 3;         // quad c -> 8 halves
        agm[p] = g_xh + (size_t)toks[r] * Hd + c * 8;
        ggm[p] = wgE + (size_t)(n0 + r) * Hd + c * 8;
        ugm[p] = wuE + (size_t)(n0 + r) * Hd + c * 8;
        soff[p] = r * G1_ROWB + c * 16;
    }
    uint32_t smb = smem_u32(bufs);

    float cg[4][4][4] = {}, cu[4][4][4] = {};

    // prologue: chunk 0 -> buf 0
#pragma unroll
    for (int p = 0; p < 2; p++) {
        CP16(smb + soff[p],               agm[p]);
        CP16(smb + G1_MATB + soff[p],     ggm[p]);
        CP16(smb + 2 * G1_MATB + soff[p], ugm[p]);
    }
    cp_commit();

    const int NCH = Hd / 32;  // 32
    for (int ch = 0; ch < NCH; ch++) {
        int buf = ch & 1;
        if (ch + 1 < NCH) {
            int k0 = (ch + 1) * 32;
            uint32_t base = smb + (buf ^ 1) * G1_BUFB;
#pragma unroll
            for (int p = 0; p < 2; p++) {
                CP16(base + soff[p],               agm[p] + k0);
                CP16(base + G1_MATB + soff[p],     ggm[p] + k0);
                CP16(base + 2 * G1_MATB + soff[p], ugm[p] + k0);
            }
            cp_commit();
            cp_wait1();
        } else {
            cp_wait0();
        }
        __syncthreads();

        const uint32_t* A  = (const uint32_t*)(bufs + buf * G1_BUFB);         // 20 words/row
        const uint32_t* Bg = (const uint32_t*)(bufs + buf * G1_BUFB + G1_MATB);
        const uint32_t* Bu = (const uint32_t*)(bufs + buf * G1_BUFB + 2 * G1_MATB);
#pragma unroll
        for (int kk = 0; kk < 2; kk++) {       // two k16 steps
            int w0 = kk * 8;                   // word offset within row
            uint32_t a[4][4];
#pragma unroll
            for (int i = 0; i < 4; i++) {
                int r = warp_m * 64 + i * 16 + g;
                a[i][0] = A[r * 20 + w0 + tig];
                a[i][1] = A[(r + 8) * 20 + w0 + tig];
                a[i][2] = A[r * 20 + w0 + tig + 4];
                a[i][3] = A[(r + 8) * 20 + w0 + tig + 4];
            }
#pragma unroll
            for (int j = 0; j < 4; j++) {
                int n = warp_n * 32 + j * 8 + g;
                uint32_t bg0 = Bg[n * 20 + w0 + tig], bg1 = Bg[n * 20 + w0 + tig + 4];
                uint32_t bu0 = Bu[n * 20 + w0 + tig], bu1 = Bu[n * 20 + w0 + tig + 4];
#pragma unroll
                for (int i = 0; i < 4; i++) {
                    MMA_F16(cg[i][j], a[i], bg0, bg1);
                    MMA_F16(cu[i][j], a[i], bu0, bu1);
                }
            }
        }
        __syncthreads();
    }

    // epilogue: silu(gate)*up -> g_hidden_h (half2 stores; pair cols are contiguous)
#pragma unroll
    for (int i = 0; i < 4; i++) {
        int rb = m0 + warp_m * 64 + i * 16 + g;
#pragma unroll
        for (int j = 0; j < 4; j++) {
            int n = n0 + warp_n * 32 + j * 8 + 2 * tig;
            if (rb < cnt) {
                size_t base = (size_t)(off + rb) * Id + n;
                float g0 = cg[i][j][0], g1 = cg[i][j][1];
                float h0 = g0 / (1.f + expf(-g0)) * cu[i][j][0];
                float h1 = g1 / (1.f + expf(-g1)) * cu[i][j][1];
                *(__half2*)(g_hidden_h + base) = __floats2half2_rn(h0, h1);
            }
            if (rb + 8 < cnt) {
                size_t base = (size_t)(off + rb + 8) * Id + n;
                float g2 = cg[i][j][2], g3 = cg[i][j][3];
                float h2 = g2 / (1.f + expf(-g2)) * cu[i][j][2];
                float h3 = g3 / (1.f + expf(-g3)) * cu[i][j][3];
                *(__half2*)(g_hidden_h + base) = __floats2half2_rn(h2, h3);
            }
        }
    }
}

// ================= GEMM2 (fp16 MMA): down = hidden @ wd^T =================
// CTA 256m x 128n, K-chunk 32 halves. 8 warps = 4m x 2n; warp 64m x 64n.
// Buf: A[256][40] | B[128][40]
#define G2_AB (256 * G1_ROWB)                 // 20480 B
#define G2_BB (128 * G1_ROWB)                 // 10240 B
#define G2_BUFB (G2_AB + G2_BB)               // 30720 B
#define G2_SMEM (2 * G2_BUFB)                 // 61440 B
__global__ void __launch_bounds__(256) k_gemm2() {
    int e   = blockIdx.z;
    int cnt = g_count[e];
    int m0  = blockIdx.x * 256;
    if (m0 >= cnt) return;
    int off = g_offset[e];
    int n0  = blockIdx.y * 128;

    extern __shared__ char smc[];
    char* bufs = smc;

    int tid = threadIdx.x;
    int lane = tid & 31, wid = tid >> 5;
    int warp_m = wid & 3, warp_n = wid >> 2;   // 4 x 2
    int g = lane >> 2, tig = lane & 3;

    const __half* wdE = g_wdh + (size_t)e * Hd * Id;
    // A: 256 rows x 4 quads = 1024 slots (4/thread); B: 512 slots (2/thread)
    const __half* agm[4]; uint32_t aoff[4];
    const __half* bgm[2]; uint32_t boff[2];
#pragma unroll
    for (int p = 0; p < 4; p++) {
        int idx = tid + 256 * p;
        int r = idx >> 2, c = idx & 3;
        int am = m0 + r; if (am >= cnt) am = cnt - 1;
        agm[p] = g_hidden_h + (size_t)(off + am) * Id + c * 8;
        aoff[p] = r * G1_ROWB + c * 16;
    }
#pragma unroll
    for (int p = 0; p < 2; p++) {
        int idx = tid + 256 * p;
        int r = idx >> 2, c = idx & 3;
        bgm[p] = wdE + (size_t)(n0 + r) * Id + c * 8;
        boff[p] = G2_AB + r * G1_ROWB + c * 16;
    }
    uint32_t smb = smem_u32(bufs);

    float c[4][8][4] = {};

#pragma unroll
    for (int p = 0; p < 4; p++) CP16(smb + aoff[p], agm[p]);
#pragma unroll
    for (int p = 0; p < 2; p++) CP16(smb + boff[p], bgm[p]);
    cp_commit();

    const int NCH = Id / 32;  // 128
    for (int ch = 0; ch < NCH; ch++) {
        int buf = ch & 1;
        if (ch + 1 < NCH) {
            int k0 = (ch + 1) * 32;
            uint32_t base = smb + (buf ^ 1) * G2_BUFB;
#pragma unroll
            for (int p = 0; p < 4; p++) CP16(base + aoff[p], agm[p] + k0);
#pragma unroll
            for (int p = 0; p < 2; p++) CP16(base + boff[p], bgm[p] + k0);
            cp_commit();
            cp_wait1();
        } else {
            cp_wait0();
        }
        __syncthreads();

        const uint32_t* A = (const uint32_t*)(bufs + buf * G2_BUFB);
        const uint32_t* B = (const uint32_t*)(bufs + buf * G2_BUFB + G2_AB);
#pragma unroll
        for (int kk = 0; kk < 2; kk++) {
            int w0 = kk * 8;
            uint32_t a[4][4];
#pragma unroll
            for (int i = 0; i < 4; i++) {
                int r = warp_m * 64 + i * 16 + g;
                a[i][0] = A[r * 20 + w0 + tig];
                a[i][1] = A[(r + 8) * 20 + w0 + tig];
                a[i][2] = A[r * 20 + w0 + tig + 4];
                a[i][3] = A[(r + 8) * 20 + w0 + tig + 4];
            }
#pragma unroll
            for (int j = 0; j < 8; j++) {
                int n = warp_n * 64 + j * 8 + g;
                uint32_t b0 = B[n * 20 + w0 + tig], b1 = B[n * 20 + w0 + tig + 4];
#pragma unroll
                for (int i = 0; i < 4; i++) MMA_F16(c[i][j], a[i], b0, b1);
            }
        }
        __syncthreads();
    }

#pragma unroll
    for (int i = 0; i < 4; i++) {
        int rb = m0 + warp_m * 64 + i * 16 + g;
#pragma unroll
        for (int j = 0; j < 8; j++) {
            int n = n0 + warp_n * 64 + j * 8 + 2 * tig;
            if (rb < cnt) {
                size_t base = (size_t)(off + rb) * Hd + n;
                g_down[base]     = c[i][j][0];
                g_down[base + 1] = c[i][j][1];
            }
            if (rb + 8 < cnt) {
                size_t base = (size_t)(off + rb + 8) * Hd + n;
                g_down[base]     = c[i][j][2];
                g_down[base + 1] = c[i][j][3];
            }
        }
    }
}

// ---------------- combine ----------------
__global__ void __launch_bounds__(256) k_combine(float* __restrict__ out) {
    int idx = blockIdx.x * 256 + threadIdx.x;
    int t   = idx >> 8;
    int c4  = (idx & 255) << 2;
    int r0  = g_tok_row[t * 2];
    int r1  = g_tok_row[t * 2 + 1];
    float w0 = g_top_w[t * 2];
    float w1 = g_top_w[t * 2 + 1];
    float4 d0 = *(const float4*)(g_down + (size_t)r0 * Hd + c4);
    float4 d1 = *(const float4*)(g_down + (size_t)r1 * Hd + c4);
    float4 o;
    o.x = w0 * d0.x + w1 * d1.x;
    o.y = w0 * d0.y + w1 * d1.y;
    o.z = w0 * d0.z + w1 * d1.z;
    o.w = w0 * d0.w + w1 * d1.w;
    *(float4*)(out + (size_t)t * Hd + c4) = o;
}

// ---------------- launch ----------------
extern "C" void kernel_launch(void* const* d_in, const int* in_sizes, int n_in,
                              void* d_out, int out_size) {
    const float* x  = (const float*)d_in[0];
    const float* gw = (const float*)d_in[1];
    const float* wg = (const float*)d_in[2];
    const float* wu = (const float*)d_in[3];
    const float* wd = (const float*)d_in[4];
    float* out = (float*)d_out;

    cudaFuncSetAttribute(k_gemm1, cudaFuncAttributeMaxDynamicSharedMemorySize, G1_SMEM);
    cudaFuncSetAttribute(k_gemm2, cudaFuncAttributeMaxDynamicSharedMemorySize, G2_SMEM);

    // fp32 -> fp16 conversions (kernels write the __device__ symbols directly)
    const int xw8 = Tn * Hd / 8;             // 524288
    const int ww8 = Ed * Id * Hd / 8;        // 4194304
    k_cvt_x <<<(xw8 + 255) / 256, 256>>>(x);
    k_cvt_wg<<<(ww8 + 255) / 256, 256>>>(wg);
    k_cvt_wu<<<(ww8 + 255) / 256, 256>>>(wu);
    k_cvt_wd<<<(ww8 + 255) / 256, 256>>>(wd);

    k_init<<<1, 32>>>();
    k_router<<<Tn / 8, 256>>>(x, gw);
    k_scan<<<1, 1>>>();
    k_assign<<<Tn / 256, 256>>>();

    dim3 g1(32, 32, Ed);   // m-tiles(128) x n-tiles(128 over I) x experts (early-exit)
    k_gemm1<<<g1, 256, G1_SMEM>>>();

    dim3 g2(16, 8, Ed);    // m-tiles(256) x n-tiles(128 over H) x experts (early-exit)
    k_gemm2<<<g2, 256, G2_SMEM>>>();

    k_combine<<<Tn * Hd / 1024, 256>>>(out);
}